// round 17
// baseline (speedup 1.0000x reference)
#include <cuda_runtime.h>
#include <cuda_fp16.h>
#include <cstdint>

#define NN 32768
typedef __half fp16;

// ======================= static scratch (__device__ globals) =======================
__device__ __align__(16) fp16 g_s [(size_t)NN * 448];
__device__ __align__(16) fp16 g_h [(size_t)NN * 448];
__device__ __align__(16) fp16 g_sg[(size_t)NN * 448];
__device__ __align__(16) float g_g1o[(size_t)NN * 128];
// weights transposed W'[n][k], n zero-padded to BN=128 multiples
__device__ __align__(16) fp16 g_w1 [512 * 448];
__device__ __align__(16) fp16 g_w2 [640 * 448];
__device__ __align__(16) fp16 g_wl0[256 * 448];

__device__ __forceinline__ uint32_t smem_u32(const void* p) {
    uint32_t a;
    asm("{ .reg .u64 t; cvta.to.shared.u64 t, %1; cvt.u32.u64 %0, t; }" : "=r"(a) : "l"(p));
    return a;
}

#define CP_ASYNC16(dst_u32, src_ptr) \
    asm volatile("cp.async.cg.shared.global [%0], [%1], 16;" \
                 :: "r"(dst_u32), "l"(src_ptr) : "memory")
#define CP_COMMIT()  asm volatile("cp.async.commit_group;" ::: "memory")
#define CP_WAIT1()   asm volatile("cp.async.wait_group 1;" ::: "memory")
#define CP_WAIT0()   asm volatile("cp.async.wait_group 0;" ::: "memory")

#define LDM4(r, addr) \
    asm volatile("ldmatrix.sync.aligned.m8n8.x4.shared.b16 {%0,%1,%2,%3}, [%4];" \
        : "=r"((r)[0]), "=r"((r)[1]), "=r"((r)[2]), "=r"((r)[3]) : "r"(addr))

#define MMA16816(d, a, b0r, b1r) \
    asm volatile("mma.sync.aligned.m16n8k16.row.col.f32.f16.f16.f32 " \
        "{%0,%1,%2,%3}, {%4,%5,%6,%7}, {%8,%9}, {%0,%1,%2,%3};" \
        : "+f"((d)[0]), "+f"((d)[1]), "+f"((d)[2]), "+f"((d)[3]) \
        : "r"((a)[0]), "r"((a)[1]), "r"((a)[2]), "r"((a)[3]), "r"(b0r), "r"(b1r))

// ======================= prep: x -> s (fp16, 448) =======================
__global__ void prep_split_kernel(const float* __restrict__ x) {
    const float ISQ3 = 0.57735026918962576f;
    const float SQ2  = 1.41421356237309505f;
    int n = blockIdx.x;
    int j = threadIdx.x;
    float val;
    if (j < 256) {
        val = x[(size_t)n * 640 + j];
    } else {
        int jj = j - 256;
        int g = jj / 3;
        int i = jj - 3 * g;
        const float* p = x + (size_t)n * 640 + 256 + 6 * g;
        float ax = p[0], ay = p[1], az = p[2];
        float bx = p[3], by = p[4], bz = p[5];
        if (i == 0)      val = (ax*ax + ay*ay + az*az) * ISQ3;
        else if (i == 1) val = SQ2 * (ax*bx + ay*by + az*bz) * ISQ3;
        else             val = (bx*bx + by*by + bz*bz) * ISQ3;
    }
    g_s[(size_t)n * 448 + j] = __float2half_rn(val);
}

// ======================= prep: tiled transpose + quantize + zero-pad =======================
__global__ void __launch_bounds__(256)
prep_w_kernel(const float* __restrict__ W1, const float* __restrict__ W2,
              const float* __restrict__ Wl0) {
    __shared__ float sm[32][33];
    const float* src; fp16* dst; int ldsrc, ncols, npad;
    if (blockIdx.z == 0)      { src = W1;  dst = g_w1;  ldsrc = 448; ncols = 448; npad = 512; }
    else if (blockIdx.z == 1) { src = W2;  dst = g_w2;  ldsrc = 832; ncols = 576; npad = 640; }
    else                      { src = Wl0; dst = g_wl0; ldsrc = 256; ncols = 256; npad = 256; }
    const int n0 = blockIdx.x * 32;
    const int k0 = blockIdx.y * 32;
    if (n0 >= npad) return;
    const int tx = threadIdx.x, ty = threadIdx.y;   // 32 x 8
#pragma unroll
    for (int rr = 0; rr < 4; rr++) {
        int kk = ty * 4 + rr;
        int n = n0 + tx;
        sm[kk][tx] = (n < ncols) ? src[(size_t)(k0 + kk) * ldsrc + n] : 0.f;
    }
    __syncthreads();
#pragma unroll
    for (int rr = 0; rr < 4; rr++) {
        int n = n0 + ty * 4 + rr;
        if (n < npad)
            dst[(size_t)n * 448 + k0 + tx] = __float2half_rn(sm[tx][ty * 4 + rr]);
    }
}

// ======================= mma.sync fp16 GEMM (TN, K=448, 128x128 tile, 512 thr) =======================
// 16 warps (4M x 4N), warp tile 32x32 (acc 32 regs) -> 2 blocks/SM, 32 warps/SM.
// 3-stage cp.async, one barrier per iteration.
// EPI: 1 = silu -> oh fp16 (gn<448);
//      2 = gn<448: sg = s*gate -> oh ; 448<=gn<576: g1o fp32 -> outf (ld 128).
template <int EPI>
__global__ void __launch_bounds__(512, 2)
mma_gemm(const fp16* __restrict__ A, const fp16* __restrict__ B,
         float scale, float* __restrict__ outf, fp16* __restrict__ oh,
         const fp16* __restrict__ sin_) {
    constexpr int ROWB = 144;
    constexpr int STG  = 256 * ROWB;           // 36864 per stage
    extern __shared__ __align__(16) char smem[];
    const uint32_t sb = smem_u32(smem);

    const int tid  = threadIdx.x;
    const int lane = tid & 31;
    const int wid  = tid >> 5;
    const int wm   = wid >> 2;                 // 0..3
    const int wn   = wid & 3;                  // 0..3
    const int bm   = blockIdx.y * 128;
    const int bn   = blockIdx.x * 128;

    const int pr = tid >> 3;                   // 0..63
    const int pq = tid & 7;

    float acc[2][4][4];
#pragma unroll
    for (int i = 0; i < 2; i++)
#pragma unroll
        for (int j = 0; j < 4; j++)
#pragma unroll
            for (int l = 0; l < 4; l++) acc[i][j][l] = 0.f;

    const int lrow  = lane & 15;
    const int lkoff = (lane >> 4) * 8;
    const uint32_t a_off = (uint32_t)((wm * 32 + lrow) * ROWB + lkoff * 2);
    const uint32_t b_row0 = (uint32_t)(128 * ROWB + (wn * 32 + lrow) * ROWB + lkoff * 2);

    auto issue = [&](int c) {
        const int k0 = c * 64;
        const uint32_t base = sb + (uint32_t)(c % 3) * STG;
#pragma unroll
        for (int j = 0; j < 2; j++) {
            int row = pr + 64 * j;
            const fp16* src = A + (size_t)(bm + row) * 448 + k0 + pq * 8;
            CP_ASYNC16(base + row * ROWB + pq * 16, src);
        }
#pragma unroll
        for (int j = 0; j < 2; j++) {
            int row = pr + 64 * j;
            const fp16* src = B + (size_t)(bn + row) * 448 + k0 + pq * 8;
            CP_ASYNC16(base + 128 * ROWB + row * ROWB + pq * 16, src);
        }
        CP_COMMIT();
    };

    issue(0); issue(1);
    for (int kt = 0; kt < 7; kt++) {
        if (kt < 6) CP_WAIT1(); else CP_WAIT0();
        __syncthreads();
        if (kt + 2 < 7) issue(kt + 2);         // buffer (kt-1)%3, reads done pre-barrier

        const uint32_t base = sb + (uint32_t)(kt % 3) * STG;
#pragma unroll
        for (int ks = 0; ks < 4; ks++) {
            uint32_t a0[4], a1[4], b0[4], b1[4];
            LDM4(a0, base + a_off + ks * 32);
            LDM4(a1, base + a_off + 16 * ROWB + ks * 32);
            LDM4(b0, base + b_row0 + ks * 32);
            LDM4(b1, base + b_row0 + 16 * ROWB + ks * 32);
            MMA16816(acc[0][0], a0, b0[0], b0[2]);
            MMA16816(acc[0][1], a0, b0[1], b0[3]);
            MMA16816(acc[0][2], a0, b1[0], b1[2]);
            MMA16816(acc[0][3], a0, b1[1], b1[3]);
            MMA16816(acc[1][0], a1, b0[0], b0[2]);
            MMA16816(acc[1][1], a1, b0[1], b0[3]);
            MMA16816(acc[1][2], a1, b1[0], b1[2]);
            MMA16816(acc[1][3], a1, b1[1], b1[3]);
        }
    }

    // ---- epilogue ----
    const int crow = lane >> 2;
    const int ccol = (lane & 3) * 2;
#pragma unroll
    for (int mf = 0; mf < 2; mf++) {
#pragma unroll
        for (int nt = 0; nt < 4; nt++) {
            const int gn = bn + wn * 32 + nt * 8 + ccol;
#pragma unroll
            for (int half = 0; half < 2; half++) {
                const int gm = bm + wm * 32 + mf * 16 + crow + half * 8;
                float v0 = acc[mf][nt][half * 2]     * scale;
                float v1 = acc[mf][nt][half * 2 + 1] * scale;
                if (EPI == 1) {
                    if (gn < 448) {
                        v0 = v0 / (1.f + expf(-v0));
                        v1 = v1 / (1.f + expf(-v1));
                        *(__half2*)&oh[(size_t)gm * 448 + gn] =
                            __half2(__float2half_rn(v0), __float2half_rn(v1));
                    }
                } else {
                    if (gn < 448) {
                        size_t o = (size_t)gm * 448 + gn;
                        __half2 sv = *(const __half2*)&sin_[o];
                        float s0 = __half2float(sv.x);
                        float s1 = __half2float(sv.y);
                        *(__half2*)&oh[o] =
                            __half2(__float2half_rn(s0 * v0), __float2half_rn(s1 * v1));
                    } else if (gn < 576) {
                        *(float2*)&outf[(size_t)gm * 128 + gn - 448] = make_float2(v0, v1);
                    }
                }
            }
        }
    }
}

// ======================= GEMM3 + fused LayerNorm =======================
// o0 = sg @ Wl0^T / sqrt(448), then per-row LayerNorm(256) -> out[:, :256].
// Block = 128 rows x ALL 256 cols. 512 threads, 16 warps (4M x 4N), warp 32x64.
__global__ void __launch_bounds__(512)
gemm3_ln(const fp16* __restrict__ A, const fp16* __restrict__ B,
         float scale, float* __restrict__ outf) {
    constexpr int ROWB = 144;
    constexpr int STG  = (128 + 256) * ROWB;   // 55296 per stage
    extern __shared__ __align__(16) char smem[];
    const uint32_t sb = smem_u32(smem);
    float* rs = (float*)(smem + 2 * STG);      // [128] row sums
    float* rq = rs + 128;                      // [128] row sumsq

    const int tid  = threadIdx.x;
    const int lane = tid & 31;
    const int wid  = tid >> 5;
    const int wm   = wid >> 2;                 // 0..3
    const int wn   = wid & 3;                  // 0..3
    const int bm   = blockIdx.x * 128;

    if (tid < 256) ((float*)(smem + 2 * STG))[tid] = 0.f;

    const int pr = tid >> 3;                   // 0..63
    const int pq = tid & 7;

    float acc[2][8][4];
#pragma unroll
    for (int i = 0; i < 2; i++)
#pragma unroll
        for (int j = 0; j < 8; j++)
#pragma unroll
            for (int l = 0; l < 4; l++) acc[i][j][l] = 0.f;

    const int lrow  = lane & 15;
    const int lkoff = (lane >> 4) * 8;
    const uint32_t a_off = (uint32_t)((wm * 32 + lrow) * ROWB + lkoff * 2);
    const uint32_t b_row0 = (uint32_t)(128 * ROWB + (wn * 64 + lrow) * ROWB + lkoff * 2);

    auto issue = [&](int c) {
        const int k0 = c * 64;
        const uint32_t base = sb + (uint32_t)(c & 1) * STG;
#pragma unroll
        for (int j = 0; j < 2; j++) {
            int row = pr + 64 * j;
            const fp16* src = A + (size_t)(bm + row) * 448 + k0 + pq * 8;
            CP_ASYNC16(base + row * ROWB + pq * 16, src);
        }
#pragma unroll
        for (int j = 0; j < 4; j++) {
            int row = pr + 64 * j;
            const fp16* src = B + (size_t)row * 448 + k0 + pq * 8;
            CP_ASYNC16(base + 128 * ROWB + row * ROWB + pq * 16, src);
        }
        CP_COMMIT();
    };

    issue(0);
    for (int kt = 0; kt < 7; kt++) {
        if (kt < 6) { issue(kt + 1); CP_WAIT1(); }
        else        { CP_WAIT0(); }
        __syncthreads();

        const uint32_t base = sb + (uint32_t)(kt & 1) * STG;
#pragma unroll
        for (int ks = 0; ks < 4; ks++) {
            uint32_t a0[4], a1[4];
            LDM4(a0, base + a_off + ks * 32);
            LDM4(a1, base + a_off + 16 * ROWB + ks * 32);
#pragma unroll
            for (int nt = 0; nt < 4; nt++) {
                uint32_t b[4];
                LDM4(b, base + b_row0 + nt * 16 * ROWB + ks * 32);
                MMA16816(acc[0][2 * nt],     a0, b[0], b[2]);
                MMA16816(acc[0][2 * nt + 1], a0, b[1], b[3]);
                MMA16816(acc[1][2 * nt],     a1, b[0], b[2]);
                MMA16816(acc[1][2 * nt + 1], a1, b[1], b[3]);
            }
        }
        __syncthreads();
    }

    const int crow = lane >> 2;
    const int ccol = (lane & 3) * 2;
#pragma unroll
    for (int mf = 0; mf < 2; mf++)
#pragma unroll
        for (int half = 0; half < 2; half++) {
            float s = 0.f, q = 0.f;
#pragma unroll
            for (int noct = 0; noct < 8; noct++) {
                float v0 = acc[mf][noct][half * 2]     * scale;
                float v1 = acc[mf][noct][half * 2 + 1] * scale;
                s += v0 + v1;
                q = fmaf(v0, v0, fmaf(v1, v1, q));
            }
            s += __shfl_xor_sync(0xffffffffu, s, 1);
            s += __shfl_xor_sync(0xffffffffu, s, 2);
            q += __shfl_xor_sync(0xffffffffu, q, 1);
            q += __shfl_xor_sync(0xffffffffu, q, 2);
            if ((lane & 3) == 0) {
                int row = wm * 32 + mf * 16 + crow + half * 8;
                atomicAdd(&rs[row], s);
                atomicAdd(&rq[row], q);
            }
        }
    __syncthreads();

#pragma unroll
    for (int mf = 0; mf < 2; mf++)
#pragma unroll
        for (int half = 0; half < 2; half++) {
            const int row = wm * 32 + mf * 16 + crow + half * 8;
            const float mean = rs[row] * (1.f / 256.f);
            float var = rq[row] * (1.f / 256.f) - mean * mean;
            const float ri = rsqrtf(var + 1e-6f);
            const int gm = bm + row;
#pragma unroll
            for (int noct = 0; noct < 8; noct++) {
                const int gn = wn * 64 + noct * 8 + ccol;
                float v0 = (acc[mf][noct][half * 2]     * scale - mean) * ri;
                float v1 = (acc[mf][noct][half * 2 + 1] * scale - mean) * ri;
                *(float2*)&outf[(size_t)gm * 640 + gn] = make_float2(v0, v1);
            }
        }
}

// ======================= tensorized o1 + RMS (plain fp16, K=128) =======================
__global__ void __launch_bounds__(256)
gate_o1_mma(const float* __restrict__ x, const float* __restrict__ Wl1,
            const float* __restrict__ g1o, float* __restrict__ out) {
    constexpr int AROW = 272;                        // 256B data + 16 pad
    constexpr uint32_t B_OFF = 192 * AROW;           // 52224
    constexpr uint32_t P_OFF = 99072;                // after o1f overlay (192*129*4)
    constexpr uint32_t R_OFF = P_OFF + 256 * 4;
    extern __shared__ __align__(16) char smem[];
    const uint32_t sb = smem_u32(smem);

    const int tid  = threadIdx.x;
    const int lane = tid & 31;
    const int wid  = tid >> 5;
    const int wm   = wid >> 1;
    const int wn   = wid & 1;
    const int n0   = blockIdx.x * 64;

    for (int idx = tid; idx < 128 * 128; idx += 256) {
        int m = idx >> 7, k = idx & 127;
        *(fp16*)(smem + B_OFF + k * AROW + m * 2) = __float2half_rn(Wl1[idx]);
    }
#pragma unroll 4
    for (int j = 0; j < 96; j++) {
        int idx = tid + j * 256;
        int nl = idx / 384;
        int r  = idx - nl * 384;
        int m  = r / 3;
        int i  = r - m * 3;
        float val = x[(size_t)(n0 + nl) * 640 + 256 + r] *
                    g1o[(size_t)(n0 + nl) * 128 + m];
        *(fp16*)(smem + (3 * nl + i) * AROW + m * 2) = __float2half_rn(val);
    }
    __syncthreads();

    const int lrow  = lane & 15;
    const int lkb   = (lane >> 4) * 16;
    float acc[3][8][4];
#pragma unroll
    for (int a = 0; a < 3; a++)
#pragma unroll
        for (int b = 0; b < 8; b++)
#pragma unroll
            for (int c = 0; c < 4; c++) acc[a][b][c] = 0.f;

#pragma unroll
    for (int kk = 0; kk < 8; kk++) {
        const int kb = kk * 32 + lkb;
        uint32_t a[3][4];
#pragma unroll
        for (int mt = 0; mt < 3; mt++)
            LDM4(a[mt], sb + (wm * 48 + mt * 16 + lrow) * AROW + kb);
#pragma unroll
        for (int nt = 0; nt < 4; nt++) {
            uint32_t b[4];
            LDM4(b, sb + B_OFF + (wn * 64 + nt * 16 + lrow) * AROW + kb);
#pragma unroll
            for (int mt = 0; mt < 3; mt++) {
                MMA16816(acc[mt][nt * 2],     a[mt], b[0], b[2]);
                MMA16816(acc[mt][nt * 2 + 1], a[mt], b[1], b[3]);
            }
        }
    }
    __syncthreads();

    float* o1f = (float*)smem;
    float* Pf  = (float*)(smem + P_OFF);
    float* Rf  = (float*)(smem + R_OFF);
    const float sc = 0.08838834764831845f;
    const int crow = lane >> 2;
    const int ccol = (lane & 3) * 2;
#pragma unroll
    for (int mt = 0; mt < 3; mt++)
#pragma unroll
        for (int nt = 0; nt < 8; nt++)
#pragma unroll
            for (int hf = 0; hf < 2; hf++) {
                int row = wm * 48 + mt * 16 + crow + hf * 8;
                int col = wn * 64 + nt * 8 + ccol;
                o1f[row * 129 + col]     = acc[mt][nt][hf * 2]     * sc;
                o1f[row * 129 + col + 1] = acc[mt][nt][hf * 2 + 1] * sc;
            }
    __syncthreads();

    {
        int nl = tid >> 2, q = tid & 3;
        float ss = 0.f;
#pragma unroll
        for (int rr = 0; rr < 3; rr++) {
            const float* rp = o1f + (3 * nl + rr) * 129 + q * 32;
#pragma unroll 8
            for (int c = 0; c < 32; c++) ss = fmaf(rp[c], rp[c], ss);
        }
        Pf[tid] = ss;
    }
    __syncthreads();
    if (tid < 64)
        Rf[tid] = rsqrtf((Pf[tid * 4] + Pf[tid * 4 + 1] + Pf[tid * 4 + 2] + Pf[tid * 4 + 3])
                         * (1.f / 384.f) + 1e-6f);
    __syncthreads();

#pragma unroll 4
    for (int j = 0; j < 96; j++) {
        int idx = tid + j * 256;
        int nl = idx / 384;
        int r  = idx - nl * 384;
        int k  = r / 3;
        int i  = r - k * 3;
        out[(size_t)(n0 + nl) * 640 + 256 + r] = o1f[(3 * nl + i) * 129 + k] * Rf[nl];
    }
}

// ======================= launch =======================
extern "C" void kernel_launch(void* const* d_in, const int* in_sizes, int n_in,
                              void* d_out, int out_size) {
    const float* x   = (const float*)d_in[0];   // [32768, 640]
    const float* W1  = (const float*)d_in[1];   // [448, 448]
    const float* W2  = (const float*)d_in[2];   // [448, 832]
    const float* Wl0 = (const float*)d_in[3];   // [448, 256]
    const float* Wl1 = (const float*)d_in[4];   // [128, 128]
    float* out = (float*)d_out;                 // [32768, 640]

    fp16 *s, *h, *sg, *w1, *w2, *wl0;
    float* g1o;
    cudaGetSymbolAddress((void**)&s,   g_s);
    cudaGetSymbolAddress((void**)&h,   g_h);
    cudaGetSymbolAddress((void**)&sg,  g_sg);
    cudaGetSymbolAddress((void**)&g1o, g_g1o);
    cudaGetSymbolAddress((void**)&w1,  g_w1);
    cudaGetSymbolAddress((void**)&w2,  g_w2);
    cudaGetSymbolAddress((void**)&wl0, g_wl0);

    const float inv_fan = 0.04724555652982141f;  // 1/sqrt(448)
    const int GEMM_SMEM = 3 * 36864;             // 110592
    const int G3_SMEM   = 2 * 55296 + 1024;      // 111616
    const int GO_SMEM   = 99072 + 1024 + 256;    // 100352

    cudaFuncSetAttribute(mma_gemm<1>, cudaFuncAttributeMaxDynamicSharedMemorySize, GEMM_SMEM);
    cudaFuncSetAttribute(mma_gemm<2>, cudaFuncAttributeMaxDynamicSharedMemorySize, GEMM_SMEM);
    cudaFuncSetAttribute(gemm3_ln,    cudaFuncAttributeMaxDynamicSharedMemorySize, G3_SMEM);
    cudaFuncSetAttribute(gate_o1_mma, cudaFuncAttributeMaxDynamicSharedMemorySize, GO_SMEM);

    prep_split_kernel<<<NN, 448>>>(x);
    prep_w_kernel<<<dim3(20, 14, 3), dim3(32, 8)>>>(W1, W2, Wl0);

    // GEMM1: h = silu(s @ W1 / sqrt(448))   [N=448, padded 512]
    mma_gemm<1><<<dim3(4, NN / 128), 512, GEMM_SMEM>>>(s, w1, inv_fan, nullptr, h, nullptr);

    // GEMM2: gates; gn<448 -> sg = s*gate, 448<=gn<576 -> g1o   [N=576, padded 640]
    mma_gemm<2><<<dim3(5, NN / 128), 512, GEMM_SMEM>>>(h, w2, inv_fan, g1o, sg, s);

    // o1 + RMS -> out[:, 256:640]  (tensorized, plain fp16)
    gate_o1_mma<<<NN / 64, 256, GO_SMEM>>>(x, Wl1, g1o, out);

    // GEMM3 + LayerNorm -> out[:, :256]
    gemm3_ln<<<NN / 128, 512, G3_SMEM>>>(sg, wl0, inv_fan, out);
}